// round 1
// baseline (speedup 1.0000x reference)
#include <cuda_runtime.h>
#include <math.h>

// Problem constants (match reference_code)
#define BB   2
#define HH   112
#define WW   112
#define HW   (HH * WW)        // 12544
#define NPIX (BB * HW)        // 25088
#define EPSV 1e-7f
// Inclusion threshold for scatter: g >= 0.69  <=>  q <= eps - ln(0.69)
// (slightly below the 0.70 output threshold so boundary rounding matches ref)
#define QMAX 0.3710637f

__global__ void zero_kernel(float* out, int n) {
    int i = blockIdx.x * blockDim.x + threadIdx.x;
    if (i < n) out[i] = 0.0f;
}

// One thread per candidate center point. Selected points render their
// anisotropic gaussian only inside its >=0.69 support window and
// atomicMax (float-as-int, values are non-negative) into the output plane.
__global__ void scatter_kernel(const float* __restrict__ variance,
                               const float* __restrict__ center,
                               float* __restrict__ out) {
    int t = blockIdx.x * blockDim.x + threadIdx.x;
    if (t >= NPIX) return;
    int b = t / HW;
    int p = t - b * HW;

    float cm = center[b * HW + p];
    float m  = (cm > 0.7f) ? 1.0f : 0.0f;

    const float* vb = variance + (size_t)b * 3 * HW;
    float vx = vb[p] * m;
    float vy = vb[HW + p] * m;
    if (vx + vy == 0.0f) return;   // matches torch.nonzero(vx+vy) selection

    float v2    = vb[2 * HW + p];
    float theta = 3.14f * (1.0f / (1.0f + expf(-v2)));
    float s, co;
    __sincosf(theta, &s, &co);
    // use precise sin/cos to track XLA more closely
    s  = sinf(theta);
    co = cosf(theta);

    float var_x = vx * vx + EPSV;
    float var_y = vy * vy + EPSV;
    float a  = co * co / (2.0f * var_x) + s * s / (2.0f * var_y);
    float bq = -2.0f * s * co / (4.0f * var_x) + 2.0f * s * co / (4.0f * var_y);
    float c  = s * s / (2.0f * var_x) + co * co / (2.0f * var_y);

    int pr = p / WW;
    int pc = p - pr * WW;

    // q >= (di^2+dj^2) / (2*max(var_x,var_y))  =>  support radius bound
    float maxvar = fmaxf(var_x, var_y);
    int R = (int)ceilf(sqrtf(2.0f * QMAX * maxvar)) + 1;
    if (R > 111) R = 111;

    int i0 = max(0, pr - R), i1 = min(HH - 1, pr + R);
    int j0 = max(0, pc - R), j1 = min(WW - 1, pc + R);

    int* outb = (int*)(out + (size_t)b * HW);
    for (int i = i0; i <= i1; ++i) {
        float di  = (float)(i - pr);
        float adi = a * di * di;
        float bdi = 2.0f * bq * di;
        for (int j = j0; j <= j1; ++j) {
            float dj = (float)(j - pc);
            float q  = adi + bdi * dj + c * dj * dj;
            if (q > QMAX) continue;            // g < 0.69: can never matter
            float g = expf(-q + EPSV);
            atomicMax(&outb[i * WW + j], __float_as_int(g));
        }
    }
}

__global__ void threshold_kernel(float* out, int n) {
    int i = blockIdx.x * blockDim.x + threadIdx.x;
    if (i < n) {
        float v = out[i];
        out[i] = (v >= 0.7f) ? v : 0.0f;
    }
}

extern "C" void kernel_launch(void* const* d_in, const int* in_sizes, int n_in,
                              void* d_out, int out_size) {
    // metadata order: x, variance, center_map, conv_w, conv_b
    const float* variance = (const float*)d_in[1];
    const float* center   = (const float*)d_in[2];
    float* out            = (float*)d_out;

    // Zero the whole output (covers the [B,1,H,W] map and the flag=False tail,
    // if the harness packs it).
    int nz = out_size;
    zero_kernel<<<(nz + 255) / 256, 256>>>(out, nz);

    scatter_kernel<<<(NPIX + 255) / 256, 256>>>(variance, center, out);

    threshold_kernel<<<(NPIX + 255) / 256, 256>>>(out, NPIX);
}